// round 13
// baseline (speedup 1.0000x reference)
#include <cuda_runtime.h>
#include <cuda_fp16.h>
#include <math.h>

// Problem constants (fixed shapes from the reference)
#define HH 64
#define WW 96
#define DD 64
#define VV 4
#define CC 16
#define EPSF 1e-8f

// -------- device scratch (allocation-free per harness rules) --------
__device__ float  g_P[VV * 12];               // (K @ E)[:3,:] per view, row-major 3x4
__device__ float  g_invK[9];                  // cur_invK[:3,:3]
__device__ float  g_depth[DD];                // inverse-depth-interpolated planes
__device__ __align__(16) __half g_srcT[VV * HH * WW * CC];  // src feats, fp16, (V,H,W,C)
__device__ __align__(16) __half g_curT[HH * WW * CC];       // cur feats, fp16, (H,W,C)

// -------- fused transpose + setup --------
__global__ void prep_kernel(const float* __restrict__ src_feats,
                            const float* __restrict__ cur_feats,
                            const float* __restrict__ src_extrinsics,
                            const float* __restrict__ src_Ks,
                            const float* __restrict__ cur_invK,
                            const float* __restrict__ min_depth,
                            const float* __restrict__ max_depth) {
    __shared__ float sh[WW * 17];  // [w][c] with pad (conflict-free)
    int b = blockIdx.x;
    int tid = threadIdx.x;  // 256 threads

    if (b == VV * HH + HH) {
        // ---- setup block ----
        if (tid < DD) {
            float inv_min = 1.0f / min_depth[0];
            float inv_max = 1.0f / max_depth[0];
            float ramp = (float)tid / (float)(DD - 1);
            g_depth[tid] = 1.0f / (inv_min + (inv_max - inv_min) * ramp);
        }
        if (tid < VV) {
            const float* K = src_Ks + tid * 16;
            const float* E = src_extrinsics + tid * 16;
            #pragma unroll
            for (int i = 0; i < 3; i++) {
                #pragma unroll
                for (int j = 0; j < 4; j++) {
                    float s = 0.0f;
                    #pragma unroll
                    for (int k = 0; k < 4; k++) s += K[i * 4 + k] * E[k * 4 + j];
                    g_P[tid * 12 + i * 4 + j] = s;
                }
            }
        }
        if (tid == 0) {
            #pragma unroll
            for (int r = 0; r < 3; r++)
                #pragma unroll
                for (int c = 0; c < 3; c++)
                    g_invK[r * 3 + c] = cur_invK[r * 4 + c];
        }
        return;
    }

    bool is_src = (b < VV * HH);
    const float* in;
    __half* outp;
    if (is_src) {
        int v = b >> 6;          // / HH
        int h = b & (HH - 1);
        in = src_feats + ((size_t)v * CC) * (HH * WW) + (size_t)h * WW;
        outp = g_srcT + ((size_t)b * WW << 4);   // b = v*HH + h
    } else {
        int h = b - VV * HH;
        in = cur_feats + (size_t)h * WW;
        outp = g_curT + ((size_t)h * WW << 4);
    }

    // load: i = c*WW + w (coalesced along w), write sh[w*17 + c]
    #pragma unroll
    for (int i = tid; i < CC * WW; i += 256) {
        int c = i / WW;
        int w = i - c * WW;
        sh[w * 17 + c] = in[(size_t)c * (HH * WW) + w];
    }
    __syncthreads();
    // store: j -> (w = j>>4, c = j&15), contiguous half writes
    #pragma unroll
    for (int j = tid; j < WW * CC; j += 256) {
        int w = j >> 4;
        int c = j & 15;
        outp[j] = __float2half(sh[w * 17 + c]);
    }
}

// -------- main cost-volume kernel --------
// Warp tile = 8 w x 4 d (lane = w_sub + 8*d_sub); each thread owns 2 depths
// (d = dbase + 4*j + d_sub). Narrow lane span keeps L1 lines/LDG low; 2 depths
// per thread keeps grid at 1536 blocks for ~60% occupancy.
__global__ void __launch_bounds__(128) cost_kernel(float* __restrict__ out) {
    __shared__ float sP[VV * 12];
    __shared__ float sIK[9];
    int tid = threadIdx.x;
    if (tid < VV * 12) sP[tid] = g_P[tid];
    if (tid < 9) sIK[tid] = g_invK[tid];
    __syncthreads();

    int lane = tid & 31;
    int wrp  = tid >> 5;          // 0..3
    int w_sub = lane & 7;
    int d_sub = lane >> 3;        // 0..3

    int b = blockIdx.x;           // 1536 blocks = 3 * 64 * 8
    int bw = b % 3;               // w tile (32 w's per block)
    int rem = b / 3;
    int h = rem & (HH - 1);
    int dt = rem >> 6;            // 0..7 -> 8 depths per block
    int dbase = dt * 8;

    int w = bw * 32 + wrp * 8 + w_sub;

    float depth[2];
    #pragma unroll
    for (int j = 0; j < 2; j++) depth[j] = g_depth[dbase + 4 * j + d_sub];

    // ray = invK[:3,:3] @ (w+0.5, h+0.5, 1)
    float px = (float)w + 0.5f;
    float py = (float)h + 0.5f;
    float rx = sIK[0] * px + sIK[1] * py + sIK[2];
    float ry = sIK[3] * px + sIK[4] * py + sIK[5];
    float rz = sIK[6] * px + sIK[7] * py + sIK[8];

    // cur feature vector: 16 half = 32B = two LDG.128 (line shared across d_sub lanes)
    float4 cA, cB;
    {
        const float4* curp = (const float4*)(g_curT + ((size_t)(h * WW + w) << 4));
        cA = curp[0];
        cB = curp[1];
    }
    const __half2* cf2a = (const __half2*)&cA;
    const __half2* cf2b = (const __half2*)&cB;

    float acc[2];
    acc[0] = 0.0f; acc[1] = 0.0f;

    #pragma unroll
    for (int v = 0; v < VV; v++) {
        const float* P = sP + v * 12;
        float qx = P[0] * rx + P[1] * ry + P[2]  * rz;
        float qy = P[4] * rx + P[5] * ry + P[6]  * rz;
        float qz = P[8] * rx + P[9] * ry + P[10] * rz;
        float tx = P[3], ty = P[7], tz = P[11];

        const __half* srcv = g_srcT + ((size_t)v * HH * WW << 4);

        #pragma unroll
        for (int j = 0; j < 2; j++) {
            float cz = fmaf(qz, depth[j], tz);
            float cx = fmaf(qx, depth[j], tx);
            float cy = fmaf(qy, depth[j], ty);
            float inv = 1.0f / (cz + EPSF);
            // x = u - 0.5, y = v - 0.5 (normalize/denormalize cancels exactly)
            float x = fmaf(cx, inv, -0.5f);
            float y = fmaf(cy, inv, -0.5f);

            float x0f = floorf(x);
            float y0f = floorf(y);
            float wx1 = x - x0f, wx0 = 1.0f - wx1;
            float wy1 = y - y0f, wy0 = 1.0f - wy1;
            int x0 = (int)x0f, y0 = (int)y0f;
            int x1 = x0 + 1,   y1 = y0 + 1;

            // validity (comparisons false on NaN/garbage coords -> weights 0)
            bool zp  = (cz > 0.0f);
            bool vx0 = zp && (x0 >= 0) && (x0 < WW);
            bool vx1 = zp && (x1 >= 0) && (x1 < WW);
            bool vy0 = (y0 >= 0) && (y0 < HH);
            bool vy1 = (y1 >= 0) && (y1 < HH);

            float m00 = (vy0 && vx0) ? wy0 * wx0 : 0.0f;
            float m01 = (vy0 && vx1) ? wy0 * wx1 : 0.0f;
            float m10 = (vy1 && vx0) ? wy1 * wx0 : 0.0f;
            float m11 = (vy1 && vx1) ? wy1 * wx1 : 0.0f;

            // clamped indices — loads issue unconditionally (no branch fences)
            int x0c = min(max(x0, 0), WW - 1);
            int x1c = min(max(x1, 0), WW - 1);
            int y0c = min(max(y0, 0), HH - 1);
            int y1c = min(max(y1, 0), HH - 1);

            const float4* p00 = (const float4*)(srcv + ((size_t)(y0c * WW + x0c) << 4));
            const float4* p01 = (const float4*)(srcv + ((size_t)(y0c * WW + x1c) << 4));
            const float4* p10 = (const float4*)(srcv + ((size_t)(y1c * WW + x0c) << 4));
            const float4* p11 = (const float4*)(srcv + ((size_t)(y1c * WW + x1c) << 4));

            // 8 independent 16B loads, front-batched
            float4 A00 = p00[0], B00 = p00[1];
            float4 A01 = p01[0], B01 = p01[1];
            float4 A10 = p10[0], B10 = p10[1];
            float4 A11 = p11[0], B11 = p11[1];

            // bilinear interp in half2 (2 channels per HFMA2)
            __half2 w00 = __float2half2_rn(m00);
            __half2 w01 = __float2half2_rn(m01);
            __half2 w10 = __float2half2_rn(m10);
            __half2 w11 = __float2half2_rn(m11);

            const __half2* h00a = (const __half2*)&A00; const __half2* h00b = (const __half2*)&B00;
            const __half2* h01a = (const __half2*)&A01; const __half2* h01b = (const __half2*)&B01;
            const __half2* h10a = (const __half2*)&A10; const __half2* h10b = (const __half2*)&B10;
            const __half2* h11a = (const __half2*)&A11; const __half2* h11b = (const __half2*)&B11;

            __half2 acc2[8];
            #pragma unroll
            for (int k = 0; k < 4; k++) {
                acc2[k]     = __hmul2(h00a[k], w00);
                acc2[k + 4] = __hmul2(h00b[k], w00);
                acc2[k]     = __hfma2(h01a[k], w01, acc2[k]);
                acc2[k + 4] = __hfma2(h01b[k], w01, acc2[k + 4]);
                acc2[k]     = __hfma2(h10a[k], w10, acc2[k]);
                acc2[k + 4] = __hfma2(h10b[k], w10, acc2[k + 4]);
                acc2[k]     = __hfma2(h11a[k], w11, acc2[k]);
                acc2[k + 4] = __hfma2(h11b[k], w11, acc2[k + 4]);
            }

            // 16-channel dot in fp32, two partial chains
            float dt0 = 0.0f, dt1 = 0.0f;
            #pragma unroll
            for (int k = 0; k < 4; k++) {
                float2 a = __half22float2(acc2[k]);
                float2 c = __half22float2(cf2a[k]);
                dt0 = fmaf(a.x, c.x, dt0);
                dt1 = fmaf(a.y, c.y, dt1);
            }
            #pragma unroll
            for (int k = 0; k < 4; k++) {
                float2 a = __half22float2(acc2[k + 4]);
                float2 c = __half22float2(cf2b[k]);
                dt0 = fmaf(a.x, c.x, dt0);
                dt1 = fmaf(a.y, c.y, dt1);
            }
            acc[j] += dt0 + dt1;
        }
    }

    #pragma unroll
    for (int j = 0; j < 2; j++) {
        int d = dbase + 4 * j + d_sub;
        out[((size_t)d * HH + h) * WW + w] = acc[j];
    }
}

extern "C" void kernel_launch(void* const* d_in, const int* in_sizes, int n_in,
                              void* d_out, int out_size) {
    const float* cur_feats      = (const float*)d_in[0];  // (B,C,H,W)
    const float* src_feats      = (const float*)d_in[1];  // (B,V,C,H,W)
    const float* src_extrinsics = (const float*)d_in[2];  // (B,V,4,4)
    const float* src_Ks         = (const float*)d_in[3];  // (B,V,4,4)
    const float* cur_invK       = (const float*)d_in[4];  // (B,4,4)
    const float* min_depth      = (const float*)d_in[5];
    const float* max_depth      = (const float*)d_in[6];
    float* out = (float*)d_out;

    prep_kernel<<<VV * HH + HH + 1, 256>>>(src_feats, cur_feats, src_extrinsics,
                                           src_Ks, cur_invK, min_depth, max_depth);

    // grid: (WW/32) * HH * (DD/8) = 3 * 64 * 8 = 1536 blocks, 128 threads
    cost_kernel<<<1536, 128>>>(out);
}

// round 14
// speedup vs baseline: 1.0942x; 1.0942x over previous
#include <cuda_runtime.h>
#include <cuda_fp16.h>
#include <math.h>

// Problem constants (fixed shapes from the reference)
#define HH 64
#define WW 96
#define DD 64
#define VV 4
#define CC 16
#define EPSF 1e-8f

// -------- device scratch (allocation-free per harness rules) --------
__device__ float  g_P[VV * 12];               // (K @ E)[:3,:] per view, row-major 3x4
__device__ float  g_invK[9];                  // cur_invK[:3,:3]
__device__ float  g_depth[DD];                // inverse-depth-interpolated planes
__device__ __align__(16) __half g_srcT[VV * HH * WW * CC];  // src feats, fp16, (V,H,W,C)
__device__ __align__(16) __half g_curT[HH * WW * CC];       // cur feats, fp16, (H,W,C)

// -------- fused transpose + setup --------
__global__ void prep_kernel(const float* __restrict__ src_feats,
                            const float* __restrict__ cur_feats,
                            const float* __restrict__ src_extrinsics,
                            const float* __restrict__ src_Ks,
                            const float* __restrict__ cur_invK,
                            const float* __restrict__ min_depth,
                            const float* __restrict__ max_depth) {
    __shared__ float sh[WW * 17];  // [w][c] with pad (conflict-free)
    int b = blockIdx.x;
    int tid = threadIdx.x;  // 256 threads

    if (b == VV * HH + HH) {
        // ---- setup block ----
        if (tid < DD) {
            float inv_min = 1.0f / min_depth[0];
            float inv_max = 1.0f / max_depth[0];
            float ramp = (float)tid / (float)(DD - 1);
            g_depth[tid] = 1.0f / (inv_min + (inv_max - inv_min) * ramp);
        }
        if (tid < VV) {
            const float* K = src_Ks + tid * 16;
            const float* E = src_extrinsics + tid * 16;
            #pragma unroll
            for (int i = 0; i < 3; i++) {
                #pragma unroll
                for (int j = 0; j < 4; j++) {
                    float s = 0.0f;
                    #pragma unroll
                    for (int k = 0; k < 4; k++) s += K[i * 4 + k] * E[k * 4 + j];
                    g_P[tid * 12 + i * 4 + j] = s;
                }
            }
        }
        if (tid == 0) {
            #pragma unroll
            for (int r = 0; r < 3; r++)
                #pragma unroll
                for (int c = 0; c < 3; c++)
                    g_invK[r * 3 + c] = cur_invK[r * 4 + c];
        }
        return;
    }

    bool is_src = (b < VV * HH);
    const float* in;
    __half* outp;
    if (is_src) {
        int v = b >> 6;          // / HH
        int h = b & (HH - 1);
        in = src_feats + ((size_t)v * CC) * (HH * WW) + (size_t)h * WW;
        outp = g_srcT + ((size_t)b * WW << 4);   // b = v*HH + h
    } else {
        int h = b - VV * HH;
        in = cur_feats + (size_t)h * WW;
        outp = g_curT + ((size_t)h * WW << 4);
    }

    // load: i = c*WW + w (coalesced along w), write sh[w*17 + c]
    #pragma unroll
    for (int i = tid; i < CC * WW; i += 256) {
        int c = i / WW;
        int w = i - c * WW;
        sh[w * 17 + c] = in[(size_t)c * (HH * WW) + w];
    }
    __syncthreads();
    // store: j -> (w = j>>4, c = j&15), contiguous half writes
    #pragma unroll
    for (int j = tid; j < WW * CC; j += 256) {
        int w = j >> 4;
        int c = j & 15;
        outp[j] = __float2half(sh[w * 17 + c]);
    }
}

// -------- main cost-volume kernel --------
// Lane = (c_half, w_sub, d_sub): c_half = lane&1, w_sub = (lane>>1)&7,
// d_sub = (lane>>4)&1. Each thread handles 8 of the 16 channels for its
// (w, d) outputs -> each corner is ONE LDG.128 per thread (lane pairs share
// the 128B line), halving gather wavefronts vs the two-chunk scheme.
// 4 depths per thread (d = dbase + 2*j + d_sub) for gather-chain ILP.
// Pair lanes combine partial dots with one shfl_xor per depth.
__global__ void __launch_bounds__(128) cost_kernel(float* __restrict__ out) {
    __shared__ float sP[VV * 12];
    __shared__ float sIK[9];
    int tid = threadIdx.x;
    if (tid < VV * 12) sP[tid] = g_P[tid];
    if (tid < 9) sIK[tid] = g_invK[tid];
    __syncthreads();

    int lane  = tid & 31;
    int wrp   = tid >> 5;            // 0..3
    int c_half = lane & 1;
    int w_sub  = (lane >> 1) & 7;
    int d_sub  = (lane >> 4) & 1;

    int b = blockIdx.x;              // 1536 blocks = 3 * 64 * 8
    int bw = b % 3;                  // w tile (32 w's per block)
    int rem = b / 3;
    int h = rem & (HH - 1);
    int dt = rem >> 6;               // 0..7 -> 8 depths per block
    int dbase = dt * 8;

    int w = bw * 32 + wrp * 8 + w_sub;

    float depth[4];
    #pragma unroll
    for (int j = 0; j < 4; j++) depth[j] = g_depth[dbase + 2 * j + d_sub];

    // ray = invK[:3,:3] @ (w+0.5, h+0.5, 1)
    float px = (float)w + 0.5f;
    float py = (float)h + 0.5f;
    float rx = sIK[0] * px + sIK[1] * py + sIK[2];
    float ry = sIK[3] * px + sIK[4] * py + sIK[5];
    float rz = sIK[6] * px + sIK[7] * py + sIK[8];

    // this thread's 8 cur channels (16B, pair lanes share the line)
    float4 cC;
    {
        const float4* curp = (const float4*)
            (g_curT + (((size_t)(h * WW + w) << 4) + (c_half << 3)));
        cC = curp[0];
    }
    const __half2* cf2 = (const __half2*)&cC;

    float acc[4];
    #pragma unroll
    for (int j = 0; j < 4; j++) acc[j] = 0.0f;

    #pragma unroll
    for (int v = 0; v < VV; v++) {
        const float* P = sP + v * 12;
        float qx = P[0] * rx + P[1] * ry + P[2]  * rz;
        float qy = P[4] * rx + P[5] * ry + P[6]  * rz;
        float qz = P[8] * rx + P[9] * ry + P[10] * rz;
        float tx = P[3], ty = P[7], tz = P[11];

        const __half* srcv = g_srcT + ((size_t)v * HH * WW << 4) + (c_half << 3);

        #pragma unroll
        for (int j = 0; j < 4; j++) {
            float cz = fmaf(qz, depth[j], tz);
            float cx = fmaf(qx, depth[j], tx);
            float cy = fmaf(qy, depth[j], ty);
            float inv = 1.0f / (cz + EPSF);
            // x = u - 0.5, y = v - 0.5 (normalize/denormalize cancels exactly)
            float x = fmaf(cx, inv, -0.5f);
            float y = fmaf(cy, inv, -0.5f);

            float x0f = floorf(x);
            float y0f = floorf(y);
            float wx1 = x - x0f, wx0 = 1.0f - wx1;
            float wy1 = y - y0f, wy0 = 1.0f - wy1;
            int x0 = (int)x0f, y0 = (int)y0f;
            int x1 = x0 + 1,   y1 = y0 + 1;

            // validity (comparisons false on NaN/garbage coords -> weights 0)
            bool zp  = (cz > 0.0f);
            bool vx0 = zp && (x0 >= 0) && (x0 < WW);
            bool vx1 = zp && (x1 >= 0) && (x1 < WW);
            bool vy0 = (y0 >= 0) && (y0 < HH);
            bool vy1 = (y1 >= 0) && (y1 < HH);

            float m00 = (vy0 && vx0) ? wy0 * wx0 : 0.0f;
            float m01 = (vy0 && vx1) ? wy0 * wx1 : 0.0f;
            float m10 = (vy1 && vx0) ? wy1 * wx0 : 0.0f;
            float m11 = (vy1 && vx1) ? wy1 * wx1 : 0.0f;

            // clamped indices — loads issue unconditionally (no branch fences)
            int x0c = min(max(x0, 0), WW - 1);
            int x1c = min(max(x1, 0), WW - 1);
            int y0c = min(max(y0, 0), HH - 1);
            int y1c = min(max(y1, 0), HH - 1);

            // ONE 16B load per corner (this thread's channel half)
            const float4* p00 = (const float4*)(srcv + ((size_t)(y0c * WW + x0c) << 4));
            const float4* p01 = (const float4*)(srcv + ((size_t)(y0c * WW + x1c) << 4));
            const float4* p10 = (const float4*)(srcv + ((size_t)(y1c * WW + x0c) << 4));
            const float4* p11 = (const float4*)(srcv + ((size_t)(y1c * WW + x1c) << 4));

            float4 A00 = p00[0];
            float4 A01 = p01[0];
            float4 A10 = p10[0];
            float4 A11 = p11[0];

            // bilinear interp in half2 (2 channels per HFMA2), 8 channels
            __half2 w00 = __float2half2_rn(m00);
            __half2 w01 = __float2half2_rn(m01);
            __half2 w10 = __float2half2_rn(m10);
            __half2 w11 = __float2half2_rn(m11);

            const __half2* h00 = (const __half2*)&A00;
            const __half2* h01 = (const __half2*)&A01;
            const __half2* h10 = (const __half2*)&A10;
            const __half2* h11 = (const __half2*)&A11;

            __half2 acc2[4];
            #pragma unroll
            for (int k = 0; k < 4; k++) {
                acc2[k] = __hmul2(h00[k], w00);
                acc2[k] = __hfma2(h01[k], w01, acc2[k]);
                acc2[k] = __hfma2(h10[k], w10, acc2[k]);
                acc2[k] = __hfma2(h11[k], w11, acc2[k]);
            }

            // 8-channel partial dot in fp32, two chains
            float dt0 = 0.0f, dt1 = 0.0f;
            #pragma unroll
            for (int k = 0; k < 4; k++) {
                float2 a = __half22float2(acc2[k]);
                float2 c = __half22float2(cf2[k]);
                dt0 = fmaf(a.x, c.x, dt0);
                dt1 = fmaf(a.y, c.y, dt1);
            }
            acc[j] += dt0 + dt1;
        }
    }

    // combine channel halves across lane pairs; c_half==0 lanes store
    #pragma unroll
    for (int j = 0; j < 4; j++) {
        float total = acc[j] + __shfl_xor_sync(0xffffffffu, acc[j], 1);
        if (c_half == 0) {
            int d = dbase + 2 * j + d_sub;
            out[((size_t)d * HH + h) * WW + w] = total;
        }
    }
}

extern "C" void kernel_launch(void* const* d_in, const int* in_sizes, int n_in,
                              void* d_out, int out_size) {
    const float* cur_feats      = (const float*)d_in[0];  // (B,C,H,W)
    const float* src_feats      = (const float*)d_in[1];  // (B,V,C,H,W)
    const float* src_extrinsics = (const float*)d_in[2];  // (B,V,4,4)
    const float* src_Ks         = (const float*)d_in[3];  // (B,V,4,4)
    const float* cur_invK       = (const float*)d_in[4];  // (B,4,4)
    const float* min_depth      = (const float*)d_in[5];
    const float* max_depth      = (const float*)d_in[6];
    float* out = (float*)d_out;

    prep_kernel<<<VV * HH + HH + 1, 256>>>(src_feats, cur_feats, src_extrinsics,
                                           src_Ks, cur_invK, min_depth, max_depth);

    // grid: (WW/32) * HH * (DD/8) = 3 * 64 * 8 = 1536 blocks, 128 threads
    cost_kernel<<<1536, 128>>>(out);
}

// round 15
// speedup vs baseline: 1.0976x; 1.0030x over previous
#include <cuda_runtime.h>
#include <cuda_fp16.h>
#include <math.h>

// Problem constants (fixed shapes from the reference)
#define HH 64
#define WW 96
#define DD 64
#define VV 4
#define CC 16
#define EPSF 1e-8f
#define HW (HH * WW)

// -------- device scratch (allocation-free per harness rules) --------
__device__ float  g_P[VV * 12];               // (K @ E)[:3,:] per view, row-major 3x4
__device__ float  g_invK[9];                  // cur_invK[:3,:3]
__device__ float  g_depth[DD];                // inverse-depth-interpolated planes
__device__ __align__(16) __half g_srcT[VV * HH * WW * CC];  // src feats, fp16, (V,H,W,C)
__device__ __align__(16) __half g_curT[HH * WW * CC];       // cur feats, fp16, (H,W,C)

// -------- fused transpose + setup --------
__global__ void prep_kernel(const float* __restrict__ src_feats,
                            const float* __restrict__ cur_feats,
                            const float* __restrict__ src_extrinsics,
                            const float* __restrict__ src_Ks,
                            const float* __restrict__ cur_invK,
                            const float* __restrict__ min_depth,
                            const float* __restrict__ max_depth) {
    __shared__ float sh[WW * 17];  // [w][c] with pad (conflict-free)
    int b = blockIdx.x;
    int tid = threadIdx.x;  // 256 threads

    if (b == VV * HH + HH) {
        // ---- setup block ----
        if (tid < DD) {
            float inv_min = 1.0f / min_depth[0];
            float inv_max = 1.0f / max_depth[0];
            float ramp = (float)tid / (float)(DD - 1);
            g_depth[tid] = 1.0f / (inv_min + (inv_max - inv_min) * ramp);
        }
        if (tid < VV) {
            const float* K = src_Ks + tid * 16;
            const float* E = src_extrinsics + tid * 16;
            #pragma unroll
            for (int i = 0; i < 3; i++) {
                #pragma unroll
                for (int j = 0; j < 4; j++) {
                    float s = 0.0f;
                    #pragma unroll
                    for (int k = 0; k < 4; k++) s += K[i * 4 + k] * E[k * 4 + j];
                    g_P[tid * 12 + i * 4 + j] = s;
                }
            }
        }
        if (tid == 0) {
            #pragma unroll
            for (int r = 0; r < 3; r++)
                #pragma unroll
                for (int c = 0; c < 3; c++)
                    g_invK[r * 3 + c] = cur_invK[r * 4 + c];
        }
        return;
    }

    bool is_src = (b < VV * HH);
    const float* in;
    __half* outp;
    if (is_src) {
        int v = b >> 6;          // / HH
        int h = b & (HH - 1);
        in = src_feats + ((size_t)v * CC) * (HH * WW) + (size_t)h * WW;
        outp = g_srcT + ((size_t)b * WW << 4);   // b = v*HH + h
    } else {
        int h = b - VV * HH;
        in = cur_feats + (size_t)h * WW;
        outp = g_curT + ((size_t)h * WW << 4);
    }

    // load: i = c*WW + w (coalesced along w), write sh[w*17 + c]
    #pragma unroll
    for (int i = tid; i < CC * WW; i += 256) {
        int c = i / WW;
        int w = i - c * WW;
        sh[w * 17 + c] = in[(size_t)c * (HH * WW) + w];
    }
    __syncthreads();
    // store: j -> (w = j>>4, c = j&15), contiguous half writes
    #pragma unroll
    for (int j = tid; j < WW * CC; j += 256) {
        int w = j >> 4;
        int c = j & 15;
        outp[j] = __float2half(sh[w * 17 + c]);
    }
}

// -------- main cost-volume kernel --------
// Lane = (c_half, w_sub, d_sub): c_half = lane&1, w_sub = (lane>>1)&7,
// d_sub = (lane>>4)&1. Each thread handles 8 of 16 channels (one LDG.128 per
// corner; lane pairs share the 128B line -> low L1 wavefronts), 2 depths per
// thread (d = dbase + 2*j + d_sub) -> 3072 blocks for high occupancy.
// Pair lanes combine partial dots with one shfl_xor per depth.
__global__ void __launch_bounds__(128) cost_kernel(float* __restrict__ out) {
    __shared__ float sP[VV * 12];
    __shared__ float sIK[9];
    int tid = threadIdx.x;
    if (tid < VV * 12) sP[tid] = g_P[tid];
    if (tid < 9) sIK[tid] = g_invK[tid];
    __syncthreads();

    int lane   = tid & 31;
    int wrp    = tid >> 5;           // 0..3
    int c_half = lane & 1;
    int w_sub  = (lane >> 1) & 7;
    int d_sub  = (lane >> 4) & 1;

    int b = blockIdx.x;              // 3072 blocks = 3 * 64 * 16
    int bw = b % 3;                  // w tile (32 w's per block)
    int rem = b / 3;
    int h = rem & (HH - 1);
    int dt = rem >> 6;               // 0..15 -> 4 depths per block
    int dbase = dt * 4;

    int w = bw * 32 + wrp * 8 + w_sub;

    float depth[2];
    depth[0] = g_depth[dbase + d_sub];
    depth[1] = g_depth[dbase + 2 + d_sub];

    // ray = invK[:3,:3] @ (w+0.5, h+0.5, 1)
    float px = (float)w + 0.5f;
    float py = (float)h + 0.5f;
    float rx = sIK[0] * px + sIK[1] * py + sIK[2];
    float ry = sIK[3] * px + sIK[4] * py + sIK[5];
    float rz = sIK[6] * px + sIK[7] * py + sIK[8];

    // this thread's 8 cur channels (16B; pair lanes share the line)
    float4 cC;
    {
        const float4* curp = (const float4*)
            (g_curT + (((h * WW + w) << 4) + (c_half << 3)));
        cC = curp[0];
    }
    const __half2* cf2 = (const __half2*)&cC;
    // hoist cur unpack to fp32 once
    float cfx[8];
    #pragma unroll
    for (int k = 0; k < 4; k++) {
        float2 c = __half22float2(cf2[k]);
        cfx[2 * k] = c.x; cfx[2 * k + 1] = c.y;
    }

    float acc[2];
    acc[0] = 0.0f; acc[1] = 0.0f;

    #pragma unroll
    for (int v = 0; v < VV; v++) {
        const float* P = sP + v * 12;
        float qx = P[0] * rx + P[1] * ry + P[2]  * rz;
        float qy = P[4] * rx + P[5] * ry + P[6]  * rz;
        float qz = P[8] * rx + P[9] * ry + P[10] * rz;
        float tx = P[3], ty = P[7], tz = P[11];

        const __half* srcv = g_srcT + ((v * HW) << 4) + (c_half << 3);

        #pragma unroll
        for (int j = 0; j < 2; j++) {
            float cz = fmaf(qz, depth[j], tz);
            float cx = fmaf(qx, depth[j], tx);
            float cy = fmaf(qy, depth[j], ty);
            float inv = 1.0f / (cz + EPSF);
            // x = u - 0.5, y = v - 0.5 (normalize/denormalize cancels exactly)
            float x = fmaf(cx, inv, -0.5f);
            float y = fmaf(cy, inv, -0.5f);

            int x0 = __float2int_rd(x);
            int y0 = __float2int_rd(y);
            float x0f = (float)x0;
            float y0f = (float)y0;
            float wx1 = x - x0f, wx0 = 1.0f - wx1;
            float wy1 = y - y0f, wy0 = 1.0f - wy1;

            // fold z>0 into y-weights; per-axis validity -> masked axis weights
            bool zp = (cz > 0.0f);
            float wy0m = (zp && y0 >= 0 && y0 < HH)          ? wy0 : 0.0f;
            float wy1m = (zp && y0 >= -1 && y0 < HH - 1)     ? wy1 : 0.0f;
            float wx0m = (x0 >= 0 && x0 < WW)                ? wx0 : 0.0f;
            float wx1m = (x0 >= -1 && x0 < WW - 1)           ? wx1 : 0.0f;

            float m00 = wy0m * wx0m;
            float m01 = wy0m * wx1m;
            float m10 = wy1m * wx0m;
            float m11 = wy1m * wx1m;

            // one linear index + 3 adds, clamped into [0, HW-1]
            // (invalid corners have zero weight; any in-bounds address is fine)
            int i00 = y0 * WW + x0;
            int i00c = min(max(i00, 0), HW - 1);
            int i01c = min(max(i00 + 1, 0), HW - 1);
            int i10c = min(max(i00 + WW, 0), HW - 1);
            int i11c = min(max(i00 + WW + 1, 0), HW - 1);

            // ONE 16B load per corner (this thread's channel half)
            float4 A00 = *(const float4*)(srcv + (i00c << 4));
            float4 A01 = *(const float4*)(srcv + (i01c << 4));
            float4 A10 = *(const float4*)(srcv + (i10c << 4));
            float4 A11 = *(const float4*)(srcv + (i11c << 4));

            // bilinear interp in half2 (2 channels per HFMA2), 8 channels
            __half2 w00 = __float2half2_rn(m00);
            __half2 w01 = __float2half2_rn(m01);
            __half2 w10 = __float2half2_rn(m10);
            __half2 w11 = __float2half2_rn(m11);

            const __half2* h00 = (const __half2*)&A00;
            const __half2* h01 = (const __half2*)&A01;
            const __half2* h10 = (const __half2*)&A10;
            const __half2* h11 = (const __half2*)&A11;

            __half2 acc2[4];
            #pragma unroll
            for (int k = 0; k < 4; k++) {
                acc2[k] = __hmul2(h00[k], w00);
                acc2[k] = __hfma2(h01[k], w01, acc2[k]);
                acc2[k] = __hfma2(h10[k], w10, acc2[k]);
                acc2[k] = __hfma2(h11[k], w11, acc2[k]);
            }

            // 8-channel partial dot in fp32, two chains
            float dt0 = 0.0f, dt1 = 0.0f;
            #pragma unroll
            for (int k = 0; k < 4; k++) {
                float2 a = __half22float2(acc2[k]);
                dt0 = fmaf(a.x, cfx[2 * k],     dt0);
                dt1 = fmaf(a.y, cfx[2 * k + 1], dt1);
            }
            acc[j] += dt0 + dt1;
        }
    }

    // combine channel halves across lane pairs; c_half==0 lanes store
    #pragma unroll
    for (int j = 0; j < 2; j++) {
        float total = acc[j] + __shfl_xor_sync(0xffffffffu, acc[j], 1);
        if (c_half == 0) {
            int d = dbase + 2 * j + d_sub;
            out[(d * HH + h) * WW + w] = total;
        }
    }
}

extern "C" void kernel_launch(void* const* d_in, const int* in_sizes, int n_in,
                              void* d_out, int out_size) {
    const float* cur_feats      = (const float*)d_in[0];  // (B,C,H,W)
    const float* src_feats      = (const float*)d_in[1];  // (B,V,C,H,W)
    const float* src_extrinsics = (const float*)d_in[2];  // (B,V,4,4)
    const float* src_Ks         = (const float*)d_in[3];  // (B,V,4,4)
    const float* cur_invK       = (const float*)d_in[4];  // (B,4,4)
    const float* min_depth      = (const float*)d_in[5];
    const float* max_depth      = (const float*)d_in[6];
    float* out = (float*)d_out;

    prep_kernel<<<VV * HH + HH + 1, 256>>>(src_feats, cur_feats, src_extrinsics,
                                           src_Ks, cur_invK, min_depth, max_depth);

    // grid: (WW/32) * HH * (DD/4) = 3 * 64 * 16 = 3072 blocks, 128 threads
    cost_kernel<<<3072, 128>>>(out);
}

// round 16
// speedup vs baseline: 1.0992x; 1.0015x over previous
#include <cuda_runtime.h>
#include <cuda_fp16.h>
#include <math.h>

// Problem constants (fixed shapes from the reference)
#define HH 64
#define WW 96
#define DD 64
#define VV 4
#define CC 16
#define EPSF 1e-8f
#define HW (HH * WW)

// -------- device scratch (allocation-free per harness rules) --------
__device__ float  g_P[VV * 12];               // (K @ E)[:3,:] per view, row-major 3x4
__device__ float  g_invK[9];                  // cur_invK[:3,:3]
__device__ float  g_depth[DD];                // inverse-depth-interpolated planes
__device__ __align__(16) __half g_srcT[VV * HH * WW * CC];  // src feats, fp16, (V,H,W,C)
__device__ __align__(16) __half g_curT[HH * WW * CC];       // cur feats, fp16, (H,W,C)

// -------- fused transpose + setup --------
__global__ void prep_kernel(const float* __restrict__ src_feats,
                            const float* __restrict__ cur_feats,
                            const float* __restrict__ src_extrinsics,
                            const float* __restrict__ src_Ks,
                            const float* __restrict__ cur_invK,
                            const float* __restrict__ min_depth,
                            const float* __restrict__ max_depth) {
    __shared__ float sh[WW * 17];  // [w][c] with pad (conflict-free)
    int b = blockIdx.x;
    int tid = threadIdx.x;  // 256 threads

    if (b == VV * HH + HH) {
        // ---- setup block ----
        if (tid < DD) {
            float inv_min = 1.0f / min_depth[0];
            float inv_max = 1.0f / max_depth[0];
            float ramp = (float)tid / (float)(DD - 1);
            g_depth[tid] = 1.0f / (inv_min + (inv_max - inv_min) * ramp);
        }
        if (tid < VV) {
            const float* K = src_Ks + tid * 16;
            const float* E = src_extrinsics + tid * 16;
            #pragma unroll
            for (int i = 0; i < 3; i++) {
                #pragma unroll
                for (int j = 0; j < 4; j++) {
                    float s = 0.0f;
                    #pragma unroll
                    for (int k = 0; k < 4; k++) s += K[i * 4 + k] * E[k * 4 + j];
                    g_P[tid * 12 + i * 4 + j] = s;
                }
            }
        }
        if (tid == 0) {
            #pragma unroll
            for (int r = 0; r < 3; r++)
                #pragma unroll
                for (int c = 0; c < 3; c++)
                    g_invK[r * 3 + c] = cur_invK[r * 4 + c];
        }
        return;
    }

    bool is_src = (b < VV * HH);
    const float* in;
    __half* outp;
    if (is_src) {
        int v = b >> 6;          // / HH
        int h = b & (HH - 1);
        in = src_feats + ((size_t)v * CC) * (HH * WW) + (size_t)h * WW;
        outp = g_srcT + ((size_t)b * WW << 4);   // b = v*HH + h
    } else {
        int h = b - VV * HH;
        in = cur_feats + (size_t)h * WW;
        outp = g_curT + ((size_t)h * WW << 4);
    }

    // load: i = c*WW + w (coalesced along w), write sh[w*17 + c]
    #pragma unroll
    for (int i = tid; i < CC * WW; i += 256) {
        int c = i / WW;
        int w = i - c * WW;
        sh[w * 17 + c] = in[(size_t)c * (HH * WW) + w];
    }
    __syncthreads();
    // store: j -> (w = j>>4, c = j&15), contiguous half writes
    #pragma unroll
    for (int j = tid; j < WW * CC; j += 256) {
        int w = j >> 4;
        int c = j & 15;
        outp[j] = __float2half(sh[w * 17 + c]);
    }
}

// -------- main cost-volume kernel --------
// Lane = (c_half, w_sub, d_sub): c_half = lane&1, w_sub = (lane>>1)&7,
// d_sub = (lane>>4)&1. Each thread handles 8 of 16 channels (one LDG.128 per
// corner; lane pairs share the 128B line -> low L1 wavefronts), 2 depths per
// thread (d = dbase + 2*j + d_sub) -> 3072 blocks for high occupancy.
// Pair lanes combine partial dots with one shfl_xor per depth.
__global__ void __launch_bounds__(128) cost_kernel(float* __restrict__ out) {
    __shared__ float sP[VV * 12];
    __shared__ float sIK[9];
    int tid = threadIdx.x;
    if (tid < VV * 12) sP[tid] = g_P[tid];
    if (tid < 9) sIK[tid] = g_invK[tid];
    __syncthreads();

    int lane   = tid & 31;
    int wrp    = tid >> 5;           // 0..3
    int c_half = lane & 1;
    int w_sub  = (lane >> 1) & 7;
    int d_sub  = (lane >> 4) & 1;

    int b = blockIdx.x;              // 3072 blocks = 3 * 64 * 16
    int bw = b % 3;                  // w tile (32 w's per block)
    int rem = b / 3;
    int h = rem & (HH - 1);
    int dt = rem >> 6;               // 0..15 -> 4 depths per block
    int dbase = dt * 4;

    int w = bw * 32 + wrp * 8 + w_sub;

    float depth[2];
    depth[0] = g_depth[dbase + d_sub];
    depth[1] = g_depth[dbase + 2 + d_sub];

    // ray = invK[:3,:3] @ (w+0.5, h+0.5, 1)
    float px = (float)w + 0.5f;
    float py = (float)h + 0.5f;
    float rx = sIK[0] * px + sIK[1] * py + sIK[2];
    float ry = sIK[3] * px + sIK[4] * py + sIK[5];
    float rz = sIK[6] * px + sIK[7] * py + sIK[8];

    // this thread's 8 cur channels (16B; pair lanes share the line)
    float4 cC;
    {
        const float4* curp = (const float4*)
            (g_curT + (((h * WW + w) << 4) + (c_half << 3)));
        cC = curp[0];
    }
    const __half2* cf2 = (const __half2*)&cC;
    // hoist cur unpack to fp32 once
    float cfx[8];
    #pragma unroll
    for (int k = 0; k < 4; k++) {
        float2 c = __half22float2(cf2[k]);
        cfx[2 * k] = c.x; cfx[2 * k + 1] = c.y;
    }

    float acc[2];
    acc[0] = 0.0f; acc[1] = 0.0f;

    #pragma unroll
    for (int v = 0; v < VV; v++) {
        const float* P = sP + v * 12;
        float qx = P[0] * rx + P[1] * ry + P[2]  * rz;
        float qy = P[4] * rx + P[5] * ry + P[6]  * rz;
        float qz = P[8] * rx + P[9] * ry + P[10] * rz;
        float tx = P[3], ty = P[7], tz = P[11];

        const __half* srcv = g_srcT + ((v * HW) << 4) + (c_half << 3);

        #pragma unroll
        for (int j = 0; j < 2; j++) {
            float cz = fmaf(qz, depth[j], tz);
            float cx = fmaf(qx, depth[j], tx);
            float cy = fmaf(qy, depth[j], ty);
            float inv = 1.0f / (cz + EPSF);
            // x = u - 0.5, y = v - 0.5 (normalize/denormalize cancels exactly)
            float x = fmaf(cx, inv, -0.5f);
            float y = fmaf(cy, inv, -0.5f);

            int x0 = __float2int_rd(x);
            int y0 = __float2int_rd(y);
            float x0f = (float)x0;
            float y0f = (float)y0;
            float wx1 = x - x0f, wx0 = 1.0f - wx1;
            float wy1 = y - y0f, wy0 = 1.0f - wy1;

            // fold z>0 into y-weights; per-axis validity -> masked axis weights
            bool zp = (cz > 0.0f);
            float wy0m = (zp && y0 >= 0 && y0 < HH)          ? wy0 : 0.0f;
            float wy1m = (zp && y0 >= -1 && y0 < HH - 1)     ? wy1 : 0.0f;
            float wx0m = (x0 >= 0 && x0 < WW)                ? wx0 : 0.0f;
            float wx1m = (x0 >= -1 && x0 < WW - 1)           ? wx1 : 0.0f;

            float m00 = wy0m * wx0m;
            float m01 = wy0m * wx1m;
            float m10 = wy1m * wx0m;
            float m11 = wy1m * wx1m;

            // one linear index + 3 adds, clamped into [0, HW-1]
            // (invalid corners have zero weight; any in-bounds address is fine)
            int i00 = y0 * WW + x0;
            int i00c = min(max(i00, 0), HW - 1);
            int i01c = min(max(i00 + 1, 0), HW - 1);
            int i10c = min(max(i00 + WW, 0), HW - 1);
            int i11c = min(max(i00 + WW + 1, 0), HW - 1);

            // ONE 16B load per corner (this thread's channel half)
            float4 A00 = *(const float4*)(srcv + (i00c << 4));
            float4 A01 = *(const float4*)(srcv + (i01c << 4));
            float4 A10 = *(const float4*)(srcv + (i10c << 4));
            float4 A11 = *(const float4*)(srcv + (i11c << 4));

            // bilinear interp in half2 (2 channels per HFMA2), 8 channels
            __half2 w00 = __float2half2_rn(m00);
            __half2 w01 = __float2half2_rn(m01);
            __half2 w10 = __float2half2_rn(m10);
            __half2 w11 = __float2half2_rn(m11);

            const __half2* h00 = (const __half2*)&A00;
            const __half2* h01 = (const __half2*)&A01;
            const __half2* h10 = (const __half2*)&A10;
            const __half2* h11 = (const __half2*)&A11;

            __half2 acc2[4];
            #pragma unroll
            for (int k = 0; k < 4; k++) {
                acc2[k] = __hmul2(h00[k], w00);
                acc2[k] = __hfma2(h01[k], w01, acc2[k]);
                acc2[k] = __hfma2(h10[k], w10, acc2[k]);
                acc2[k] = __hfma2(h11[k], w11, acc2[k]);
            }

            // 8-channel partial dot in fp32, two chains
            float dt0 = 0.0f, dt1 = 0.0f;
            #pragma unroll
            for (int k = 0; k < 4; k++) {
                float2 a = __half22float2(acc2[k]);
                dt0 = fmaf(a.x, cfx[2 * k],     dt0);
                dt1 = fmaf(a.y, cfx[2 * k + 1], dt1);
            }
            acc[j] += dt0 + dt1;
        }
    }

    // combine channel halves across lane pairs; c_half==0 lanes store
    #pragma unroll
    for (int j = 0; j < 2; j++) {
        float total = acc[j] + __shfl_xor_sync(0xffffffffu, acc[j], 1);
        if (c_half == 0) {
            int d = dbase + 2 * j + d_sub;
            out[(d * HH + h) * WW + w] = total;
        }
    }
}

extern "C" void kernel_launch(void* const* d_in, const int* in_sizes, int n_in,
                              void* d_out, int out_size) {
    const float* cur_feats      = (const float*)d_in[0];  // (B,C,H,W)
    const float* src_feats      = (const float*)d_in[1];  // (B,V,C,H,W)
    const float* src_extrinsics = (const float*)d_in[2];  // (B,V,4,4)
    const float* src_Ks         = (const float*)d_in[3];  // (B,V,4,4)
    const float* cur_invK       = (const float*)d_in[4];  // (B,4,4)
    const float* min_depth      = (const float*)d_in[5];
    const float* max_depth      = (const float*)d_in[6];
    float* out = (float*)d_out;

    prep_kernel<<<VV * HH + HH + 1, 256>>>(src_feats, cur_feats, src_extrinsics,
                                           src_Ks, cur_invK, min_depth, max_depth);

    // grid: (WW/32) * HH * (DD/4) = 3 * 64 * 16 = 3072 blocks, 128 threads
    cost_kernel<<<3072, 128>>>(out);
}